// round 2
// baseline (speedup 1.0000x reference)
#include <cuda_runtime.h>

#define NPTS     65536
#define NT       64
#define NS       32
#define NB       64
#define CHUNK    512
#define NWARP    4
#define NCOPY    2
#define NTHREADS 128
#define NCHUNKS  (NPTS / CHUNK)

#define RADIUS_F 1.1f
#define STEP_F   (2.0f * RADIUS_F / (NS - 1))
#define INVSTEP_F ((float)(NS - 1) / (2.0f * RADIUS_F))

// Global delta accumulator: [NB][NS][NT]
__device__ float g_delta[NB * NS * NT];

__global__ void zero_kernel() {
    int i = blockIdx.x * blockDim.x + threadIdx.x;
    if (i < NB * NS * NT) g_delta[i] = 0.f;
}

__device__ __forceinline__ float tanh_approx(float x) {
    float r;
    asm("tanh.approx.f32 %0, %1;" : "=f"(r) : "f"(x));
    return r;
}

// Phase 1: windowed sigmoid deltas, per-warp private smem accumulation.
// grid = (NCHUNKS, 2): x = node chunk of 512, y = theta half (32 thetas).
__global__ void __launch_bounds__(NTHREADS) ect_phase1(
    const float* __restrict__ x, const float* __restrict__ v,
    const int* __restrict__ batch)
{
    __shared__ float acc[NWARP * NCOPY * NS * 32];  // [warp][copy][s][theta_lane]
    __shared__ float xs[CHUNK * 3];
    __shared__ int   bs[CHUNK];

    const int tid  = threadIdx.x;
    const int w    = tid >> 5;
    const int lane = tid & 31;
    const int chunk = blockIdx.x;
    const int tbase = blockIdx.y << 5;
    const int t     = tbase + lane;

    for (int i = tid; i < NWARP * NCOPY * NS * 32; i += NTHREADS) acc[i] = 0.f;
    for (int i = tid; i < CHUNK * 3; i += NTHREADS)
        xs[i] = x[chunk * (CHUNK * 3) + i];
    for (int i = tid; i < CHUNK; i += NTHREADS)
        bs[i] = batch[chunk * CHUNK + i];
    __syncthreads();

    const int baseg = bs[0];
    const float v0 = v[0 * NT + t];
    const float v1 = v[1 * NT + t];
    const float v2 = v[2 * NT + t];

    float* wacc = acc + w * (NCOPY * NS * 32) + lane;
    const float hs = 50.0f * STEP_F;          // half-z step between lin samples
    const int npw = CHUNK / NWARP;

    for (int i = 0; i < npw; i++) {
        const int n = w * npw + i;
        const float x0 = xs[n * 3 + 0];
        const float x1 = xs[n * 3 + 1];
        const float x2 = xs[n * 3 + 2];
        const int c = bs[n] - baseg;

        const float nh = fmaf(x0, v0, fmaf(x1, v1, x2 * v2));
        const float sstar = (nh + RADIUS_F) * INVSTEP_F;
        const int s_lo = __float2int_rd(sstar) - 2;
        // half of z at j=0:  0.5 * 100 * (lin(s_lo) - nh)
        const float a = 50.0f * (fmaf((float)s_lo, STEP_F, -RADIUS_F) - nh);

        float prev = 0.f;
        if (c < NCOPY) {
            float* p = wacc + c * (NS * 32);
            #pragma unroll
            for (int j = 0; j < 6; j++) {
                float sig = fmaf(0.5f, tanh_approx(fmaf((float)j, hs, a)), 0.5f);
                float dlt = sig - prev; prev = sig;
                int idx = s_lo + j;
                int tgt = idx < 0 ? 0 : idx;
                if (tgt < NS) p[tgt * 32] += dlt;
            }
            int idx = s_lo + 6;
            int tgt = idx < 0 ? 0 : idx;
            if (tgt < NS) p[tgt * 32] += 1.f - prev;
        } else {
            // fallback (chunk spans >2 graphs: shouldn't happen with ~1024-node graphs)
            const int g = baseg + c;
            float* gp = g_delta + (g * NS) * NT + t;
            #pragma unroll
            for (int j = 0; j < 6; j++) {
                float sig = fmaf(0.5f, tanh_approx(fmaf((float)j, hs, a)), 0.5f);
                float dlt = sig - prev; prev = sig;
                int idx = s_lo + j;
                int tgt = idx < 0 ? 0 : idx;
                if (tgt < NS) atomicAdd(gp + tgt * NT, dlt);
            }
            int idx = s_lo + 6;
            int tgt = idx < 0 ? 0 : idx;
            if (tgt < NS) atomicAdd(gp + tgt * NT, 1.f - prev);
        }
    }
    __syncthreads();

    // Flush: sum the NWARP private copies, atomically add into g_delta.
    for (int e = tid; e < NCOPY * NS * 32; e += NTHREADS) {
        const int c  = e / (NS * 32);
        const int st = e % (NS * 32);
        float sum = 0.f;
        #pragma unroll
        for (int w2 = 0; w2 < NWARP; w2++)
            sum += acc[w2 * (NCOPY * NS * 32) + c * (NS * 32) + st];
        const int g = baseg + c;
        if (g < NB && sum != 0.f) {
            const int s = st >> 5, tl = st & 31;
            atomicAdd(&g_delta[(g * NS + s) * NT + tbase + tl], sum);
        }
    }
}

// Phase 2: prefix-sum deltas along s per (b, t) into the output.
__global__ void ect_phase2(float* __restrict__ out) {
    const int b = blockIdx.x;
    const int t = threadIdx.x;
    float run = 0.f;
    #pragma unroll
    for (int s = 0; s < NS; s++) {
        run += g_delta[(b * NS + s) * NT + t];
        out[(b * NS + s) * NT + t] = run;
    }
}

extern "C" void kernel_launch(void* const* d_in, const int* in_sizes, int n_in,
                              void* d_out, int out_size) {
    (void)in_sizes; (void)n_in; (void)out_size;
    const float* x     = (const float*)d_in[0];
    const float* v     = (const float*)d_in[1];
    // d_in[2] = lin (unused: reconstructed analytically; linspace matches to <1 ulp-scale)
    const int*   batch = (const int*)d_in[3];
    float* out = (float*)d_out;

    zero_kernel<<<(NB * NS * NT + 255) / 256, 256>>>();
    dim3 grid(NCHUNKS, NT / 32);
    ect_phase1<<<grid, NTHREADS>>>(x, v, batch);
    ect_phase2<<<NB, NT>>>(out);
}